// round 3
// baseline (speedup 1.0000x reference)
#include <cuda_runtime.h>
#include <cuda_bf16.h>
#include <cstdint>

// Problem constants
#define D        512
#define NROWS    8192
#define BHALF    4096
#define BM       128
#define BN       128
#define BK       16
#define TM       8
#define TN       8
#define NT       64                 // tiles per dimension (8192/128)
#define NTILES   2080               // NT*(NT+1)/2, bj >= bi
#define NCHUNK   32                 // row chunks for colsum (256 rows each)

// -------- device scratch (no allocations allowed) --------
__device__ float  g_sq[NROWS];
__device__ float  g_colpart[NCHUNK][D];
__device__ float  g_c16;            // log2(e) / (16*bw)
__device__ double g_partial[NTILES];

__device__ __forceinline__ float ex2_approx(float x) {
    float y;
    asm("ex2.approx.ftz.f32 %0, %1;" : "=f"(y) : "f"(x));
    return y;
}

// -------- kernel 1: per-row squared norms --------
// grid 1024, block 256 (8 warps -> 8 rows per block)
__global__ void k_rowsq(const float* __restrict__ src, const float* __restrict__ tgt) {
    int row  = blockIdx.x * 8 + (threadIdx.x >> 5);
    int lane = threadIdx.x & 31;
    const float* p = (row < BHALF) ? (src + (size_t)row * D)
                                   : (tgt + (size_t)(row - BHALF) * D);
    const float4* p4 = (const float4*)p;
    float s = 0.f;
    #pragma unroll
    for (int c = lane; c < D / 4; c += 32) {
        float4 v = p4[c];
        s += v.x * v.x + v.y * v.y + v.z * v.z + v.w * v.w;
    }
    #pragma unroll
    for (int o = 16; o; o >>= 1) s += __shfl_xor_sync(0xffffffffu, s, o);
    if (lane == 0) g_sq[row] = s;
}

// -------- kernel 2: column-sum partials (deterministic, chunked) --------
// grid 32, block 512 (one thread per column)
__global__ void k_colsum(const float* __restrict__ src, const float* __restrict__ tgt) {
    int c = blockIdx.x;
    int d = threadIdx.x;
    const float* base = (c < NCHUNK / 2) ? (src + (size_t)c * 256 * D)
                                         : (tgt + (size_t)(c - NCHUNK / 2) * 256 * D);
    float s = 0.f;
    for (int r = 0; r < 256; r++) s += base[(size_t)r * D + d];
    g_colpart[c][d] = s;
}

// -------- kernel 3: reduce scalars -> bandwidth factor --------
// 1 block, 512 threads
__global__ void k_scalar() {
    int d = threadIdx.x;
    float cs = 0.f;
    #pragma unroll
    for (int c = 0; c < NCHUNK; c++) cs += g_colpart[c][d];
    double v  = (double)cs * (double)cs;
    double sq = 0.0;
    #pragma unroll
    for (int k = 0; k < NROWS / D; k++) sq += (double)g_sq[d + D * k];

    __shared__ double s1[512], s2[512];
    s1[d] = v; s2[d] = sq;
    __syncthreads();
    for (int o = 256; o; o >>= 1) {
        if (d < o) { s1[d] += s1[d + o]; s2[d] += s2[d + o]; }
        __syncthreads();
    }
    if (d == 0) {
        double n     = (double)NROWS;
        double sumL2 = 2.0 * n * s2[0] - 2.0 * s1[0];
        double bw    = sumL2 / (n * n - n) / 4.0;   // / KERNEL_MUL^(KERNEL_NUM//2)
        g_c16 = (float)(1.4426950408889634 / (bw * 16.0));
    }
}

// -------- kernel 4: fused GEMM + multi-bandwidth RBF + signed tile reduce --------
// grid NTILES, block 256; classic 128x128x16 double-buffered SGEMM, 8x8 per thread
__global__ void __launch_bounds__(256) k_mmd_main(const float* __restrict__ src,
                                                 const float* __restrict__ tgt) {
    // linear tile id -> (bi, bj) with bj >= bi
    int t = blockIdx.x, bi = 0, rl = NT;
    while (t >= rl) { t -= rl; bi++; rl--; }
    int bj = bi + t;

    const float* Ab = (bi < NT / 2) ? (src + (size_t)bi * BM * D)
                                    : (tgt + (size_t)(bi - NT / 2) * BM * D);
    const float* Bb = (bj < NT / 2) ? (src + (size_t)bj * BN * D)
                                    : (tgt + (size_t)(bj - NT / 2) * BN * D);

    __shared__ float As[2][BK][BM];
    __shared__ float Bs[2][BK][BN];
    __shared__ float sqA[BM], sqB[BN];
    __shared__ float red[256];

    int tid = threadIdx.x;
    int tx  = tid & 15;     // 0..15 -> N
    int ty  = tid >> 4;     // 0..15 -> M

    if (tid < 128) sqA[tid]       = g_sq[bi * BM + tid];
    else           sqB[tid - 128] = g_sq[bj * BN + (tid - 128)];

    float acc[TM][TN];
    #pragma unroll
    for (int i = 0; i < TM; i++)
        #pragma unroll
        for (int j = 0; j < TN; j++) acc[i][j] = 0.f;

    // global tile load: 128 rows x 16 cols = 512 float4; 2 per thread per operand
    float4 pa[2], pb[2];
    int v0 = tid, v1 = tid + 256;
    int r0 = v0 >> 2, kq0 = (v0 & 3) * 4;
    int r1 = v1 >> 2, kq1 = (v1 & 3) * 4;

    // preload k-tile 0
    pa[0] = *(const float4*)(Ab + (size_t)r0 * D + kq0);
    pa[1] = *(const float4*)(Ab + (size_t)r1 * D + kq1);
    pb[0] = *(const float4*)(Bb + (size_t)r0 * D + kq0);
    pb[1] = *(const float4*)(Bb + (size_t)r1 * D + kq1);
    {
        As[0][kq0 + 0][r0] = pa[0].x; As[0][kq0 + 1][r0] = pa[0].y;
        As[0][kq0 + 2][r0] = pa[0].z; As[0][kq0 + 3][r0] = pa[0].w;
        As[0][kq1 + 0][r1] = pa[1].x; As[0][kq1 + 1][r1] = pa[1].y;
        As[0][kq1 + 2][r1] = pa[1].z; As[0][kq1 + 3][r1] = pa[1].w;
        Bs[0][kq0 + 0][r0] = pb[0].x; Bs[0][kq0 + 1][r0] = pb[0].y;
        Bs[0][kq0 + 2][r0] = pb[0].z; Bs[0][kq0 + 3][r0] = pb[0].w;
        Bs[0][kq1 + 0][r1] = pb[1].x; Bs[0][kq1 + 1][r1] = pb[1].y;
        Bs[0][kq1 + 2][r1] = pb[1].z; Bs[0][kq1 + 3][r1] = pb[1].w;
    }
    __syncthreads();

    int buf = 0;
    #pragma unroll 1
    for (int kt = 0; kt < D / BK; kt++) {
        if (kt < D / BK - 1) {
            int ko = (kt + 1) * BK;
            pa[0] = *(const float4*)(Ab + (size_t)r0 * D + ko + kq0);
            pa[1] = *(const float4*)(Ab + (size_t)r1 * D + ko + kq1);
            pb[0] = *(const float4*)(Bb + (size_t)r0 * D + ko + kq0);
            pb[1] = *(const float4*)(Bb + (size_t)r1 * D + ko + kq1);
        }
        #pragma unroll
        for (int k = 0; k < BK; k++) {
            float a[TM], b[TN];
            *(float4*)(a)     = *(const float4*)&As[buf][k][ty * 8];
            *(float4*)(a + 4) = *(const float4*)&As[buf][k][ty * 8 + 4];
            *(float4*)(b)     = *(const float4*)&Bs[buf][k][tx * 8];
            *(float4*)(b + 4) = *(const float4*)&Bs[buf][k][tx * 8 + 4];
            #pragma unroll
            for (int i = 0; i < TM; i++)
                #pragma unroll
                for (int j = 0; j < TN; j++)
                    acc[i][j] = fmaf(a[i], b[j], acc[i][j]);
        }
        if (kt < D / BK - 1) {
            int nb = buf ^ 1;
            As[nb][kq0 + 0][r0] = pa[0].x; As[nb][kq0 + 1][r0] = pa[0].y;
            As[nb][kq0 + 2][r0] = pa[0].z; As[nb][kq0 + 3][r0] = pa[0].w;
            As[nb][kq1 + 0][r1] = pa[1].x; As[nb][kq1 + 1][r1] = pa[1].y;
            As[nb][kq1 + 2][r1] = pa[1].z; As[nb][kq1 + 3][r1] = pa[1].w;
            Bs[nb][kq0 + 0][r0] = pb[0].x; Bs[nb][kq0 + 1][r0] = pb[0].y;
            Bs[nb][kq0 + 2][r0] = pb[0].z; Bs[nb][kq0 + 3][r0] = pb[0].w;
            Bs[nb][kq1 + 0][r1] = pb[1].x; Bs[nb][kq1 + 1][r1] = pb[1].y;
            Bs[nb][kq1 + 2][r1] = pb[1].z; Bs[nb][kq1 + 3][r1] = pb[1].w;
            __syncthreads();
            buf = nb;
        }
    }

    // epilogue: L2 -> u = exp(-L2/(16 bw)); sum_i exp(-L2/(bw*2^i)) = u+u^2+u^4+u^8+u^16
    float c16 = g_c16;
    float sa[TM], sb[TN];
    #pragma unroll
    for (int i = 0; i < TM; i++) sa[i] = sqA[ty * 8 + i];
    #pragma unroll
    for (int j = 0; j < TN; j++) sb[j] = sqB[tx * 8 + j];

    float tsum = 0.f;
    #pragma unroll
    for (int i = 0; i < TM; i++) {
        #pragma unroll
        for (int j = 0; j < TN; j++) {
            float L2  = sa[i] + sb[j] - 2.f * acc[i][j];
            float u   = ex2_approx(-L2 * c16);
            float u2  = u * u;
            float u4  = u2 * u2;
            float u8  = u4 * u4;
            float u16 = u8 * u8;
            tsum += ((u + u2) + (u4 + u8)) + u16;
        }
    }

    red[tid] = tsum;
    __syncthreads();
    #pragma unroll
    for (int o = 128; o; o >>= 1) {
        if (tid < o) red[tid] += red[tid + o];
        __syncthreads();
    }
    if (tid == 0) {
        double w = ((bi < NT / 2) == (bj < NT / 2)) ? 1.0 : -1.0;
        if (bi != bj) w *= 2.0;                  // symmetric off-diagonal tile counted twice
        g_partial[blockIdx.x] = w * (double)red[0];
    }
}

// -------- kernel 5: deterministic final reduction --------
__global__ void k_final(float* __restrict__ out) {
    __shared__ double s[256];
    int tid = threadIdx.x;
    double acc = 0.0;
    for (int i = tid; i < NTILES; i += 256) acc += g_partial[i];
    s[tid] = acc;
    __syncthreads();
    #pragma unroll
    for (int o = 128; o; o >>= 1) {
        if (tid < o) s[tid] += s[tid + o];
        __syncthreads();
    }
    if (tid == 0) out[0] = (float)(s[0] / ((double)BHALF * (double)BHALF));
}

extern "C" void kernel_launch(void* const* d_in, const int* in_sizes, int n_in,
                              void* d_out, int out_size) {
    const float* src = (const float*)d_in[0];
    const float* tgt = (const float*)d_in[1];
    float* out = (float*)d_out;

    k_rowsq<<<NROWS / 8, 256>>>(src, tgt);
    k_colsum<<<NCHUNK, 512>>>(src, tgt);
    k_scalar<<<1, 512>>>();
    k_mmd_main<<<NTILES, 256>>>(src, tgt);
    k_final<<<1, 256>>>(out);
}

// round 6
// speedup vs baseline: 2.0375x; 2.0375x over previous
#include <cuda_runtime.h>
#include <cuda_bf16.h>
#include <cstdint>

// Problem constants
#define D        512
#define NROWS    8192
#define BHALF    4096
#define BM       128
#define BN       128
#define NT       64                 // tiles per dim (8192/128)
#define NTILES   2080               // NT*(NT+1)/2, bj >= bi
#define NCHUNK   32
#define KCH      32                 // bf16 K elems per chunk
#define NCH      (D / KCH)          // 16 chunks
#define SROWB    80                 // smem row bytes: 32 bf16 (64 B) + 16 B pad
#define OPB      (128 * SROWB)      // 10240 B per operand tile
#define TOTB     (4 * OPB)          // 40960 B static smem (Ah, Al, Bh, Bl)

// -------- device scratch --------
__device__ __align__(16) __nv_bfloat16 g_hi[NROWS * D];
__device__ __align__(16) __nv_bfloat16 g_lo[NROWS * D];
__device__ float  g_sq[NROWS];
__device__ float  g_colpart[NCHUNK][D];
__device__ float  g_c16;
__device__ double g_partial[NTILES];

// -------- helpers --------
__device__ __forceinline__ uint32_t smem_u32(const void* p) {
    uint32_t a;
    asm("{ .reg .u64 t; cvta.to.shared.u64 t, %1; cvt.u32.u64 %0, t; }" : "=r"(a) : "l"(p));
    return a;
}
__device__ __forceinline__ float ex2_approx(float x) {
    float y; asm("ex2.approx.ftz.f32 %0, %1;" : "=f"(y) : "f"(x)); return y;
}
#define LDSM4(r, a) \
    asm volatile("ldmatrix.sync.aligned.m8n8.x4.shared.b16 {%0,%1,%2,%3}, [%4];" \
        : "=r"((r)[0]), "=r"((r)[1]), "=r"((r)[2]), "=r"((r)[3]) : "r"(a))
#define MMA16816(c, A, b0, b1) \
    asm volatile("mma.sync.aligned.m16n8k16.row.col.f32.bf16.bf16.f32 " \
        "{%0,%1,%2,%3}, {%4,%5,%6,%7}, {%8,%9}, {%0,%1,%2,%3};" \
        : "+f"((c)[0]), "+f"((c)[1]), "+f"((c)[2]), "+f"((c)[3]) \
        : "r"((A)[0]), "r"((A)[1]), "r"((A)[2]), "r"((A)[3]), "r"(b0), "r"(b1))

// -------- kernel 1: per-row squared norms (f32 exact) --------
__global__ void k_rowsq(const float* __restrict__ src, const float* __restrict__ tgt) {
    int row  = blockIdx.x * 8 + (threadIdx.x >> 5);
    int lane = threadIdx.x & 31;
    const float* p = (row < BHALF) ? (src + (size_t)row * D)
                                   : (tgt + (size_t)(row - BHALF) * D);
    const float4* p4 = (const float4*)p;
    float s = 0.f;
    #pragma unroll
    for (int c = lane; c < D / 4; c += 32) {
        float4 v = p4[c];
        s += v.x * v.x + v.y * v.y + v.z * v.z + v.w * v.w;
    }
    #pragma unroll
    for (int o = 16; o; o >>= 1) s += __shfl_xor_sync(0xffffffffu, s, o);
    if (lane == 0) g_sq[row] = s;
}

// -------- kernel 2: column-sum partials --------
__global__ void k_colsum(const float* __restrict__ src, const float* __restrict__ tgt) {
    int c = blockIdx.x;
    int d = threadIdx.x;
    const float* base = (c < NCHUNK / 2) ? (src + (size_t)c * 256 * D)
                                         : (tgt + (size_t)(c - NCHUNK / 2) * 256 * D);
    float s = 0.f;
    for (int r = 0; r < 256; r++) s += base[(size_t)r * D + d];
    g_colpart[c][d] = s;
}

// -------- kernel 3: bandwidth scalar --------
__global__ void k_scalar() {
    int d = threadIdx.x;
    float cs = 0.f;
    #pragma unroll
    for (int c = 0; c < NCHUNK; c++) cs += g_colpart[c][d];
    double v  = (double)cs * (double)cs;
    double sq = 0.0;
    #pragma unroll
    for (int k = 0; k < NROWS / D; k++) sq += (double)g_sq[d + D * k];
    __shared__ double s1[512], s2[512];
    s1[d] = v; s2[d] = sq;
    __syncthreads();
    for (int o = 256; o; o >>= 1) {
        if (d < o) { s1[d] += s1[d + o]; s2[d] += s2[d + o]; }
        __syncthreads();
    }
    if (d == 0) {
        double n     = (double)NROWS;
        double sumL2 = 2.0 * n * s2[0] - 2.0 * s1[0];
        double bw    = sumL2 / (n * n - n) / 4.0;
        g_c16 = (float)(1.4426950408889634 / (bw * 16.0));
    }
}

// -------- kernel 4: split f32 -> bf16 hi/lo --------
__global__ void k_split(const float* __restrict__ src, const float* __restrict__ tgt) {
    size_t gid  = (size_t)blockIdx.x * blockDim.x + threadIdx.x;
    size_t elem = gid * 4;
    const float4 v = (elem < (size_t)BHALF * D)
        ? *(const float4*)(src + elem)
        : *(const float4*)(tgt + (elem - (size_t)BHALF * D));
    float x[4] = {v.x, v.y, v.z, v.w};
    uint32_t hp[2], lp[2];
    #pragma unroll
    for (int q = 0; q < 2; q++) {
        __nv_bfloat16 h0 = __float2bfloat16_rn(x[q * 2]);
        __nv_bfloat16 h1 = __float2bfloat16_rn(x[q * 2 + 1]);
        __nv_bfloat16 l0 = __float2bfloat16_rn(x[q * 2] - __bfloat162float(h0));
        __nv_bfloat16 l1 = __float2bfloat16_rn(x[q * 2 + 1] - __bfloat162float(h1));
        hp[q] = (uint32_t)__bfloat16_as_ushort(h0) | ((uint32_t)__bfloat16_as_ushort(h1) << 16);
        lp[q] = (uint32_t)__bfloat16_as_ushort(l0) | ((uint32_t)__bfloat16_as_ushort(l1) << 16);
    }
    *(uint2*)(g_hi + elem) = make_uint2(hp[0], hp[1]);
    *(uint2*)(g_lo + elem) = make_uint2(lp[0], lp[1]);
}

// -------- kernel 5: HMMA bf16-split GEMM + RBF epilogue --------
// 256 threads, static 40 KB smem, single stage with register prefetch.
__global__ void __launch_bounds__(256) k_mmd_hmma() {
    __shared__ __align__(128) char sbuf[TOTB];
    __shared__ float sqA[BM], sqB[BN];
    __shared__ float red[256];

    int tid = threadIdx.x;
    int wid = tid >> 5, l = tid & 31;
    int warp_m = wid >> 2;          // 0..1 -> 64-row slab
    int warp_n = wid & 3;           // 0..3 -> 32-col slab

    // tile decode: blockIdx -> (bi, bj), bj >= bi
    int t = blockIdx.x, bi = 0, rl = NT;
    while (t >= rl) { t -= rl; bi++; rl--; }
    int bj = bi + t;

    uint32_t sb = smem_u32(sbuf);
    const uint32_t arow = (uint32_t)bi * BM;
    const uint32_t brow = (uint32_t)bj * BN;

    if (tid < 128) sqA[tid]       = g_sq[arow + tid];
    else           sqB[tid - 128] = g_sq[brow + (tid - 128)];

    // per-thread load slots: v = tid + i*256, i<8 -> 2048 16B transfers per chunk
    // op = v>>9 (0=Ah 1=Al 2=Bh 3=Bl), row = (v&511)>>2, seg = v&3
    const __nv_bfloat16* gptr[8];
    uint32_t sdst[8];
    #pragma unroll
    for (int i = 0; i < 8; i++) {
        int v = tid + i * 256;
        int op = v >> 9, u = v & 511;
        int row = u >> 2, seg = u & 3;
        const __nv_bfloat16* gp = (op & 1) ? g_lo : g_hi;
        uint32_t rb = (op < 2) ? arow : brow;
        gptr[i] = gp + ((size_t)(rb + row) * D + seg * 8);
        sdst[i] = sb + (uint32_t)op * OPB + (uint32_t)row * SROWB + (uint32_t)seg * 16;
    }

    // per-lane ldmatrix byte offsets within an operand tile
    uint32_t aLaneOff = (uint32_t)(warp_m * 64 + (l & 15)) * SROWB + (uint32_t)(l >> 4) * 16;
    uint32_t bLaneOff = (uint32_t)(warp_n * 32 + (l & 7) + ((l >> 4) << 3)) * SROWB
                      + (uint32_t)((l >> 3) & 1) * 16;

    float c[4][4][4];
    #pragma unroll
    for (int mi = 0; mi < 4; mi++)
        #pragma unroll
        for (int nf = 0; nf < 4; nf++)
            #pragma unroll
            for (int q = 0; q < 4; q++) c[mi][nf][q] = 0.f;

    // prefetch chunk 0 into registers
    uint4 pf[8];
    #pragma unroll
    for (int i = 0; i < 8; i++) pf[i] = *(const uint4*)(gptr[i]);

    #pragma unroll 1
    for (int kc = 0; kc < NCH; kc++) {
        // store prefetched chunk to smem
        #pragma unroll
        for (int i = 0; i < 8; i++) *(uint4*)(sbuf + (sdst[i] - sb)) = pf[i];
        __syncthreads();

        // prefetch next chunk while computing this one
        if (kc + 1 < NCH) {
            #pragma unroll
            for (int i = 0; i < 8; i++)
                pf[i] = *(const uint4*)(gptr[i] + (size_t)(kc + 1) * KCH);
        }

        uint32_t ah_b = sb + 0 * OPB + aLaneOff;
        uint32_t al_b = sb + 1 * OPB + aLaneOff;
        uint32_t bh_b = sb + 2 * OPB + bLaneOff;
        uint32_t bl_b = sb + 3 * OPB + bLaneOff;

        #pragma unroll
        for (int ks = 0; ks < 2; ks++) {
            uint32_t ko = (uint32_t)ks * 32;      // 16 bf16 = 32 B
            uint32_t Ah[4][4], Al[4][4], Bh[2][4], Bl[2][4];
            #pragma unroll
            for (int mi = 0; mi < 4; mi++) {
                LDSM4(Ah[mi], ah_b + (uint32_t)mi * (16 * SROWB) + ko);
                LDSM4(Al[mi], al_b + (uint32_t)mi * (16 * SROWB) + ko);
            }
            #pragma unroll
            for (int nj = 0; nj < 2; nj++) {
                LDSM4(Bh[nj], bh_b + (uint32_t)nj * (16 * SROWB) + ko);
                LDSM4(Bl[nj], bl_b + (uint32_t)nj * (16 * SROWB) + ko);
            }
            #pragma unroll
            for (int mi = 0; mi < 4; mi++) {
                #pragma unroll
                for (int nf = 0; nf < 4; nf++) {
                    int nj = nf >> 1, h = (nf & 1) * 2;
                    MMA16816(c[mi][nf], Ah[mi], Bh[nj][h], Bh[nj][h + 1]);
                    MMA16816(c[mi][nf], Ah[mi], Bl[nj][h], Bl[nj][h + 1]);
                    MMA16816(c[mi][nf], Al[mi], Bh[nj][h], Bh[nj][h + 1]);
                }
            }
        }
        __syncthreads();   // all reads of sbuf done before next chunk's stores
    }

    // epilogue: L2 -> u + u^2 + u^4 + u^8 + u^16 (accumulators already in regs)
    float c16 = g_c16;
    float tsum = 0.f;
    #pragma unroll
    for (int mi = 0; mi < 4; mi++) {
        int r0 = warp_m * 64 + mi * 16 + (l >> 2);
        float sa0 = sqA[r0], sa1 = sqA[r0 + 8];
        #pragma unroll
        for (int nf = 0; nf < 4; nf++) {
            int j0 = warp_n * 32 + nf * 8 + 2 * (l & 3);
            float sb0 = sqB[j0], sb1 = sqB[j0 + 1];
            #pragma unroll
            for (int q = 0; q < 4; q++) {
                float sa  = (q < 2) ? sa0 : sa1;
                float sbv = (q & 1) ? sb1 : sb0;
                float L2  = sa + sbv - 2.f * c[mi][nf][q];
                float u   = ex2_approx(-L2 * c16);
                float u2 = u * u, u4 = u2 * u2, u8 = u4 * u4, u16 = u8 * u8;
                tsum += ((u + u2) + (u4 + u8)) + u16;
            }
        }
    }

    red[tid] = tsum;
    __syncthreads();
    #pragma unroll
    for (int o = 128; o; o >>= 1) {
        if (tid < o) red[tid] += red[tid + o];
        __syncthreads();
    }
    if (tid == 0) {
        double w = ((bi < NT / 2) == (bj < NT / 2)) ? 1.0 : -1.0;
        if (bi != bj) w *= 2.0;
        g_partial[blockIdx.x] = w * (double)red[0];
    }
}

// -------- kernel 6: deterministic final reduction --------
__global__ void k_final(float* __restrict__ out) {
    __shared__ double s[256];
    int tid = threadIdx.x;
    double acc = 0.0;
    for (int i = tid; i < NTILES; i += 256) acc += g_partial[i];
    s[tid] = acc;
    __syncthreads();
    #pragma unroll
    for (int o = 128; o; o >>= 1) {
        if (tid < o) s[tid] += s[tid + o];
        __syncthreads();
    }
    if (tid == 0) out[0] = (float)(s[0] / ((double)BHALF * (double)BHALF));
}

extern "C" void kernel_launch(void* const* d_in, const int* in_sizes, int n_in,
                              void* d_out, int out_size) {
    const float* src = (const float*)d_in[0];
    const float* tgt = (const float*)d_in[1];
    float* out = (float*)d_out;

    k_rowsq<<<NROWS / 8, 256>>>(src, tgt);
    k_colsum<<<NCHUNK, 512>>>(src, tgt);
    k_scalar<<<1, 512>>>();
    k_split<<<(NROWS * D) / (256 * 4), 256>>>(src, tgt);
    k_mmd_hmma<<<NTILES, 256>>>();
    k_final<<<1, 256>>>(out);
}

// round 11
// speedup vs baseline: 3.3715x; 1.6548x over previous
#include <cuda_runtime.h>
#include <cuda_bf16.h>
#include <cstdint>

// Problem constants
#define D        512
#define NROWS    8192
#define BHALF    4096
#define BM       128
#define BN       128
#define NT       64                 // tiles per dim (8192/128)
#define NTILES   2080               // NT*(NT+1)/2, bj >= bi
#define NCHUNK   32
#define KCH      32                 // bf16 K elems per chunk
#define NCH      (D / KCH)          // 16 chunks
#define OPB      8192               // 128 rows x 64 B (swizzled, no pad)
#define STAGEB   (3 * OPB)          // Ah, Bh, Bl = 24576 B
#define TOTB     (2 * STAGEB)       // 49152 B = 48 KB static (exact limit)

// -------- device scratch --------
__device__ __align__(16) __nv_bfloat16 g_hi[NROWS * D];
__device__ __align__(16) __nv_bfloat16 g_lo[NROWS * D];
__device__ float  g_sq[NROWS];
__device__ float  g_colpart[NCHUNK][D];
__device__ float  g_c16;
__device__ double g_partial[NTILES];

// -------- helpers --------
__device__ __forceinline__ uint32_t smem_u32(const void* p) {
    uint32_t a;
    asm("{ .reg .u64 t; cvta.to.shared.u64 t, %1; cvt.u32.u64 %0, t; }" : "=r"(a) : "l"(p));
    return a;
}
__device__ __forceinline__ float ex2_approx(float x) {
    float y; asm("ex2.approx.ftz.f32 %0, %1;" : "=f"(y) : "f"(x)); return y;
}
#define LDSM4(r, a) \
    asm volatile("ldmatrix.sync.aligned.m8n8.x4.shared.b16 {%0,%1,%2,%3}, [%4];" \
        : "=r"((r)[0]), "=r"((r)[1]), "=r"((r)[2]), "=r"((r)[3]) : "r"(a))
#define MMA16816(c, A, b0, b1) \
    asm volatile("mma.sync.aligned.m16n8k16.row.col.f32.bf16.bf16.f32 " \
        "{%0,%1,%2,%3}, {%4,%5,%6,%7}, {%8,%9}, {%0,%1,%2,%3};" \
        : "+f"((c)[0]), "+f"((c)[1]), "+f"((c)[2]), "+f"((c)[3]) \
        : "r"((A)[0]), "r"((A)[1]), "r"((A)[2]), "r"((A)[3]), "r"(b0), "r"(b1))

// -------- kernel 1: per-row squared norms (f32 exact) --------
__global__ void k_rowsq(const float* __restrict__ src, const float* __restrict__ tgt) {
    int row  = blockIdx.x * 8 + (threadIdx.x >> 5);
    int lane = threadIdx.x & 31;
    const float* p = (row < BHALF) ? (src + (size_t)row * D)
                                   : (tgt + (size_t)(row - BHALF) * D);
    const float4* p4 = (const float4*)p;
    float s = 0.f;
    #pragma unroll
    for (int c = lane; c < D / 4; c += 32) {
        float4 v = p4[c];
        s += v.x * v.x + v.y * v.y + v.z * v.z + v.w * v.w;
    }
    #pragma unroll
    for (int o = 16; o; o >>= 1) s += __shfl_xor_sync(0xffffffffu, s, o);
    if (lane == 0) g_sq[row] = s;
}

// -------- kernel 2: column-sum partials --------
__global__ void k_colsum(const float* __restrict__ src, const float* __restrict__ tgt) {
    int c = blockIdx.x;
    int d = threadIdx.x;
    const float* base = (c < NCHUNK / 2) ? (src + (size_t)c * 256 * D)
                                         : (tgt + (size_t)(c - NCHUNK / 2) * 256 * D);
    float s = 0.f;
    for (int r = 0; r < 256; r++) s += base[(size_t)r * D + d];
    g_colpart[c][d] = s;
}

// -------- kernel 3: bandwidth scalar --------
__global__ void k_scalar() {
    int d = threadIdx.x;
    float cs = 0.f;
    #pragma unroll
    for (int c = 0; c < NCHUNK; c++) cs += g_colpart[c][d];
    double v  = (double)cs * (double)cs;
    double sq = 0.0;
    #pragma unroll
    for (int k = 0; k < NROWS / D; k++) sq += (double)g_sq[d + D * k];
    __shared__ double s1[512], s2[512];
    s1[d] = v; s2[d] = sq;
    __syncthreads();
    for (int o = 256; o; o >>= 1) {
        if (d < o) { s1[d] += s1[d + o]; s2[d] += s2[d + o]; }
        __syncthreads();
    }
    if (d == 0) {
        double n     = (double)NROWS;
        double sumL2 = 2.0 * n * s2[0] - 2.0 * s1[0];
        double bw    = sumL2 / (n * n - n) / 4.0;
        g_c16 = (float)(1.4426950408889634 / (bw * 16.0));
    }
}

// -------- kernel 4: split f32 -> bf16 hi/lo --------
__global__ void k_split(const float* __restrict__ src, const float* __restrict__ tgt) {
    size_t gid  = (size_t)blockIdx.x * blockDim.x + threadIdx.x;
    size_t elem = gid * 4;
    const float4 v = (elem < (size_t)BHALF * D)
        ? *(const float4*)(src + elem)
        : *(const float4*)(tgt + (elem - (size_t)BHALF * D));
    float x[4] = {v.x, v.y, v.z, v.w};
    uint32_t hp[2], lp[2];
    #pragma unroll
    for (int q = 0; q < 2; q++) {
        __nv_bfloat16 h0 = __float2bfloat16_rn(x[q * 2]);
        __nv_bfloat16 h1 = __float2bfloat16_rn(x[q * 2 + 1]);
        __nv_bfloat16 l0 = __float2bfloat16_rn(x[q * 2] - __bfloat162float(h0));
        __nv_bfloat16 l1 = __float2bfloat16_rn(x[q * 2 + 1] - __bfloat162float(h1));
        hp[q] = (uint32_t)__bfloat16_as_ushort(h0) | ((uint32_t)__bfloat16_as_ushort(h1) << 16);
        lp[q] = (uint32_t)__bfloat16_as_ushort(l0) | ((uint32_t)__bfloat16_as_ushort(l1) << 16);
    }
    *(uint2*)(g_hi + elem) = make_uint2(hp[0], hp[1]);
    *(uint2*)(g_lo + elem) = make_uint2(lp[0], lp[1]);
}

// -------- kernel 5: HMMA 2-term bf16-split GEMM + RBF epilogue --------
// 256 threads, 48 KB static smem, 2-stage pipeline, XOR-swizzled tiles.
// dot(x,y) ~= x_hi.y_hi + x_hi.y_lo  (drops x_lo.y_hi; err ~2^-9 random)
__global__ void __launch_bounds__(256) k_mmd_hmma() {
    __shared__ __align__(128) char sbuf[TOTB];

    int tid = threadIdx.x;
    int wid = tid >> 5, l = tid & 31;
    int warp_m = wid >> 2;          // 0..1 -> 64-row slab
    int warp_n = wid & 3;           // 0..3 -> 32-col slab

    // tile decode: blockIdx -> (bi, bj), bj >= bi
    int t = blockIdx.x, bi = 0, rl = NT;
    while (t >= rl) { t -= rl; bi++; rl--; }
    int bj = bi + t;

    uint32_t sb = smem_u32(sbuf);
    const uint32_t arow = (uint32_t)bi * BM;
    const uint32_t brow = (uint32_t)bj * BN;

    // per-thread load slots: v = tid + i*256, i<6 -> 1536 16B transfers per chunk
    // op = v>>9 (0=Ah 1=Bh 2=Bl), row = (v&511)>>2, seg(atom) = v&3
    const __nv_bfloat16* gptr[6];
    uint32_t soff[6];               // swizzled byte offset within a stage
    #pragma unroll
    for (int i = 0; i < 6; i++) {
        int v = tid + i * 256;
        int op = v >> 9, u = v & 511;
        int row = u >> 2, seg = u & 3;
        const __nv_bfloat16* gp = (op == 2) ? g_lo : g_hi;
        uint32_t rb = (op == 0) ? arow : brow;
        gptr[i] = gp + ((size_t)(rb + row) * D + seg * 8);
        uint32_t atom = (uint32_t)seg ^ (((uint32_t)row >> 1) & 3);
        soff[i] = (uint32_t)op * OPB + (uint32_t)row * 64 + (atom << 4);
    }

    // per-lane ldmatrix row/swizzle (invariant across mi/nj/ks)
    uint32_t rowA = (uint32_t)warp_m * 64 + (l & 15);
    uint32_t swzA = (rowA >> 1) & 3;
    uint32_t offA = rowA * 64;
    uint32_t selA = (uint32_t)(l >> 4);          // atom low bit
    uint32_t rowB = (uint32_t)warp_n * 32 + (l & 7) + ((l >> 4) << 3);
    uint32_t swzB = (rowB >> 1) & 3;
    uint32_t offB = rowB * 64;
    uint32_t selB = (uint32_t)((l >> 3) & 1);

    float c[4][4][4];
    #pragma unroll
    for (int mi = 0; mi < 4; mi++)
        #pragma unroll
        for (int nf = 0; nf < 4; nf++)
            #pragma unroll
            for (int q = 0; q < 4; q++) c[mi][nf][q] = 0.f;

    // prologue: chunk 0 -> stage 0
    uint4 pf[6];
    #pragma unroll
    for (int i = 0; i < 6; i++) pf[i] = *(const uint4*)(gptr[i]);
    #pragma unroll
    for (int i = 0; i < 6; i++) *(uint4*)(sbuf + soff[i]) = pf[i];
    __syncthreads();

    #pragma unroll 1
    for (int kc = 0; kc < NCH; kc++) {
        uint32_t stage = (uint32_t)(kc & 1) * STAGEB;
        // prefetch next chunk while computing this one
        if (kc + 1 < NCH) {
            #pragma unroll
            for (int i = 0; i < 6; i++)
                pf[i] = *(const uint4*)(gptr[i] + (size_t)(kc + 1) * KCH);
        }

        uint32_t ah_t = sb + stage + offA;
        uint32_t bh_t = sb + stage + OPB + offB;
        uint32_t bl_t = sb + stage + 2 * OPB + offB;

        #pragma unroll
        for (int ks = 0; ks < 2; ks++) {
            uint32_t atomA = ((uint32_t)ks * 2 + selA) ^ swzA;
            uint32_t atomB = ((uint32_t)ks * 2 + selB) ^ swzB;
            uint32_t Ah[4][4], Bh[2][4], Bl[2][4];
            #pragma unroll
            for (int mi = 0; mi < 4; mi++)
                LDSM4(Ah[mi], ah_t + (uint32_t)mi * 1024 + (atomA << 4));
            #pragma unroll
            for (int nj = 0; nj < 2; nj++) {
                LDSM4(Bh[nj], bh_t + (uint32_t)nj * 1024 + (atomB << 4));
                LDSM4(Bl[nj], bl_t + (uint32_t)nj * 1024 + (atomB << 4));
            }
            #pragma unroll
            for (int mi = 0; mi < 4; mi++) {
                #pragma unroll
                for (int nf = 0; nf < 4; nf++) {
                    int nj = nf >> 1, h = (nf & 1) * 2;
                    MMA16816(c[mi][nf], Ah[mi], Bh[nj][h], Bh[nj][h + 1]);
                    MMA16816(c[mi][nf], Ah[mi], Bl[nj][h], Bl[nj][h + 1]);
                }
            }
        }

        // store next chunk into the other stage
        if (kc + 1 < NCH) {
            uint32_t nst = (uint32_t)((kc + 1) & 1) * STAGEB;
            #pragma unroll
            for (int i = 0; i < 6; i++) *(uint4*)(sbuf + nst + soff[i]) = pf[i];
        }
        __syncthreads();
    }

    // epilogue: L2 -> u + u^2 + u^4 + u^8 + u^16 (sq norms straight from L2)
    float c16 = g_c16;
    float tsum = 0.f;
    #pragma unroll
    for (int mi = 0; mi < 4; mi++) {
        int r0 = warp_m * 64 + mi * 16 + (l >> 2);
        float sa0 = g_sq[arow + r0], sa1 = g_sq[arow + r0 + 8];
        #pragma unroll
        for (int nf = 0; nf < 4; nf++) {
            int j0 = warp_n * 32 + nf * 8 + 2 * (l & 3);
            float sb0 = g_sq[brow + j0], sb1 = g_sq[brow + j0 + 1];
            #pragma unroll
            for (int q = 0; q < 4; q++) {
                float sa  = (q < 2) ? sa0 : sa1;
                float sbv = (q & 1) ? sb1 : sb0;
                float L2  = sa + sbv - 2.f * c[mi][nf][q];
                float u   = ex2_approx(-L2 * c16);
                float u2 = u * u, u4 = u2 * u2, u8 = u4 * u4, u16 = u8 * u8;
                tsum += ((u + u2) + (u4 + u8)) + u16;
            }
        }
    }

    // warp shfl reduce, then 8 partials via reused sbuf
    #pragma unroll
    for (int o = 16; o; o >>= 1) tsum += __shfl_xor_sync(0xffffffffu, tsum, o);
    float* red = (float*)sbuf;
    __syncthreads();                 // mainloop smem reads complete (already synced, safe)
    if (l == 0) red[wid] = tsum;
    __syncthreads();
    if (tid == 0) {
        float s = 0.f;
        #pragma unroll
        for (int w = 0; w < 8; w++) s += red[w];
        double wt = ((bi < NT / 2) == (bj < NT / 2)) ? 1.0 : -1.0;
        if (bi != bj) wt *= 2.0;
        g_partial[blockIdx.x] = wt * (double)s;
    }
}

// -------- kernel 6: deterministic final reduction --------
__global__ void k_final(float* __restrict__ out) {
    __shared__ double s[256];
    int tid = threadIdx.x;
    double acc = 0.0;
    for (int i = tid; i < NTILES; i += 256) acc += g_partial[i];
    s[tid] = acc;
    __syncthreads();
    #pragma unroll
    for (int o = 128; o; o >>= 1) {
        if (tid < o) s[tid] += s[tid + o];
        __syncthreads();
    }
    if (tid == 0) out[0] = (float)(s[0] / ((double)BHALF * (double)BHALF));
}

extern "C" void kernel_launch(void* const* d_in, const int* in_sizes, int n_in,
                              void* d_out, int out_size) {
    const float* src = (const float*)d_in[0];
    const float* tgt = (const float*)d_in[1];
    float* out = (float*)d_out;

    k_rowsq<<<NROWS / 8, 256>>>(src, tgt);
    k_colsum<<<NCHUNK, 512>>>(src, tgt);
    k_scalar<<<1, 512>>>();
    k_split<<<(NROWS * D) / (256 * 4), 256>>>(src, tgt);
    k_mmd_hmma<<<NTILES, 256>>>();
    k_final<<<1, 256>>>(out);
}

// round 12
// speedup vs baseline: 4.1479x; 1.2303x over previous
#include <cuda_runtime.h>
#include <cuda_bf16.h>
#include <cstdint>

// Problem constants
#define D        512
#define NROWS    8192
#define BHALF    4096
#define BM       128
#define BN       128
#define NT       64                 // tiles per dim (8192/128)
#define NTILES   2080               // NT*(NT+1)/2, bj >= bi
#define NCHUNK   32
#define KCH      32                 // bf16 K elems per chunk
#define NCH      (D / KCH)          // 16 chunks
#define OPB      8192               // 128 rows x 64 B (swizzled, no pad)
#define STAGEB   (3 * OPB)          // Ah, Bh, Bl = 24576 B
#define TOTB     (2 * STAGEB)       // 49152 B = 48 KB static

// -------- device scratch --------
__device__ __align__(16) __nv_bfloat16 g_hi[NROWS * D];
__device__ __align__(16) __nv_bfloat16 g_lo[NROWS * D];
__device__ float  g_sq[NROWS];
__device__ float  g_colpart[NCHUNK][D];
__device__ float  g_c16;
__device__ double g_partial[NTILES];

// -------- helpers --------
__device__ __forceinline__ uint32_t smem_u32(const void* p) {
    uint32_t a;
    asm("{ .reg .u64 t; cvta.to.shared.u64 t, %1; cvt.u32.u64 %0, t; }" : "=r"(a) : "l"(p));
    return a;
}
__device__ __forceinline__ float ex2_approx(float x) {
    float y; asm("ex2.approx.ftz.f32 %0, %1;" : "=f"(y) : "f"(x)); return y;
}
#define LDSM4(r, a) \
    asm volatile("ldmatrix.sync.aligned.m8n8.x4.shared.b16 {%0,%1,%2,%3}, [%4];" \
        : "=r"((r)[0]), "=r"((r)[1]), "=r"((r)[2]), "=r"((r)[3]) : "r"(a))
#define MMA16816(c, A, b0, b1) \
    asm volatile("mma.sync.aligned.m16n8k16.row.col.f32.bf16.bf16.f32 " \
        "{%0,%1,%2,%3}, {%4,%5,%6,%7}, {%8,%9}, {%0,%1,%2,%3};" \
        : "+f"((c)[0]), "+f"((c)[1]), "+f"((c)[2]), "+f"((c)[3]) \
        : "r"((A)[0]), "r"((A)[1]), "r"((A)[2]), "r"((A)[3]), "r"(b0), "r"(b1))
#define CP_ASYNC16(dst, src) \
    asm volatile("cp.async.cg.shared.global [%0], [%1], 16;" :: "r"(dst), "l"(src) : "memory")
#define CP_COMMIT()  asm volatile("cp.async.commit_group;" ::: "memory")
#define CP_WAIT0()   asm volatile("cp.async.wait_group 0;" ::: "memory")

// -------- kernel 1: fused per-row sq-norm + bf16 hi/lo split (one 32MB pass) ----
// grid 1024, block 256: 8 warps -> 8 rows per block
__global__ void k_prep(const float* __restrict__ src, const float* __restrict__ tgt) {
    int row  = blockIdx.x * 8 + (threadIdx.x >> 5);
    int lane = threadIdx.x & 31;
    const float* p = (row < BHALF) ? (src + (size_t)row * D)
                                   : (tgt + (size_t)(row - BHALF) * D);
    const float4* p4 = (const float4*)p;
    float s = 0.f;
    #pragma unroll
    for (int c = lane; c < D / 4; c += 32) {
        float4 v = p4[c];
        s += v.x * v.x + v.y * v.y + v.z * v.z + v.w * v.w;
        float x[4] = {v.x, v.y, v.z, v.w};
        uint32_t hp[2], lp[2];
        #pragma unroll
        for (int q = 0; q < 2; q++) {
            __nv_bfloat16 h0 = __float2bfloat16_rn(x[q * 2]);
            __nv_bfloat16 h1 = __float2bfloat16_rn(x[q * 2 + 1]);
            __nv_bfloat16 l0 = __float2bfloat16_rn(x[q * 2] - __bfloat162float(h0));
            __nv_bfloat16 l1 = __float2bfloat16_rn(x[q * 2 + 1] - __bfloat162float(h1));
            hp[q] = (uint32_t)__bfloat16_as_ushort(h0) | ((uint32_t)__bfloat16_as_ushort(h1) << 16);
            lp[q] = (uint32_t)__bfloat16_as_ushort(l0) | ((uint32_t)__bfloat16_as_ushort(l1) << 16);
        }
        size_t elem = (size_t)row * D + (size_t)c * 4;
        *(uint2*)(g_hi + elem) = make_uint2(hp[0], hp[1]);
        *(uint2*)(g_lo + elem) = make_uint2(lp[0], lp[1]);
    }
    #pragma unroll
    for (int o = 16; o; o >>= 1) s += __shfl_xor_sync(0xffffffffu, s, o);
    if (lane == 0) g_sq[row] = s;
}

// -------- kernel 2: column-sum partials --------
__global__ void k_colsum(const float* __restrict__ src, const float* __restrict__ tgt) {
    int c = blockIdx.x;
    int d = threadIdx.x;
    const float* base = (c < NCHUNK / 2) ? (src + (size_t)c * 256 * D)
                                         : (tgt + (size_t)(c - NCHUNK / 2) * 256 * D);
    float s = 0.f;
    for (int r = 0; r < 256; r++) s += base[(size_t)r * D + d];
    g_colpart[c][d] = s;
}

// -------- kernel 3: bandwidth scalar --------
__global__ void k_scalar() {
    int d = threadIdx.x;
    float cs = 0.f;
    #pragma unroll
    for (int c = 0; c < NCHUNK; c++) cs += g_colpart[c][d];
    double v  = (double)cs * (double)cs;
    double sq = 0.0;
    #pragma unroll
    for (int k = 0; k < NROWS / D; k++) sq += (double)g_sq[d + D * k];
    __shared__ double s1[512], s2[512];
    s1[d] = v; s2[d] = sq;
    __syncthreads();
    for (int o = 256; o; o >>= 1) {
        if (d < o) { s1[d] += s1[d + o]; s2[d] += s2[d + o]; }
        __syncthreads();
    }
    if (d == 0) {
        double n     = (double)NROWS;
        double sumL2 = 2.0 * n * s2[0] - 2.0 * s1[0];
        double bw    = sumL2 / (n * n - n) / 4.0;
        g_c16 = (float)(1.4426950408889634 / (bw * 16.0));
    }
}

// -------- kernel 4: HMMA 2-term bf16-split GEMM + RBF epilogue --------
// 256 threads, 48 KB static smem, 2-stage cp.async pipeline, 2 CTAs/SM.
// dot(x,y) ~= x_hi.y_hi + x_hi.y_lo
__global__ void __launch_bounds__(256, 2) k_mmd_hmma() {
    __shared__ __align__(128) char sbuf[TOTB];

    int tid = threadIdx.x;
    int wid = tid >> 5, l = tid & 31;
    int warp_m = wid >> 2;          // 0..1 -> 64-row slab
    int warp_n = wid & 3;           // 0..3 -> 32-col slab

    // tile decode: blockIdx -> (bi, bj), bj >= bi
    int t = blockIdx.x, bi = 0, rl = NT;
    while (t >= rl) { t -= rl; bi++; rl--; }
    int bj = bi + t;

    uint32_t sb = smem_u32(sbuf);
    const uint32_t arow = (uint32_t)bi * BM;
    const uint32_t brow = (uint32_t)bj * BN;

    // loader: thread -> (r = tid>>2 in 0..63, seg = tid&3); 6 slots:
    //   Ah rows r, r+64 ; Bh rows r, r+64 ; Bl rows r, r+64
    int r   = tid >> 2, seg = tid & 3;
    uint32_t atom = (uint32_t)seg ^ (((uint32_t)r >> 1) & 3);
    uint32_t aoff = (uint32_t)r * 64 + (atom << 4);
    const __nv_bfloat16* gA  = g_hi + ((size_t)(arow + r) * D + seg * 8);
    const __nv_bfloat16* gBh = g_hi + ((size_t)(brow + r) * D + seg * 8);
    const __nv_bfloat16* gBl = g_lo + ((size_t)(brow + r) * D + seg * 8);
    const size_t RSTEP = (size_t)64 * D;   // +64 rows

    // per-lane ldmatrix row/swizzle
    uint32_t rowA = (uint32_t)warp_m * 64 + (l & 15);
    uint32_t swzA = (rowA >> 1) & 3;
    uint32_t offA = rowA * 64;
    uint32_t selA = (uint32_t)(l >> 4);
    uint32_t rowB = (uint32_t)warp_n * 32 + (l & 7) + ((l >> 4) << 3);
    uint32_t swzB = (rowB >> 1) & 3;
    uint32_t offB = rowB * 64;
    uint32_t selB = (uint32_t)((l >> 3) & 1);

    float c[4][4][4];
    #pragma unroll
    for (int mi = 0; mi < 4; mi++)
        #pragma unroll
        for (int nf = 0; nf < 4; nf++)
            #pragma unroll
            for (int q = 0; q < 4; q++) c[mi][nf][q] = 0.f;

    // prologue: issue chunk 0 into stage 0
    {
        uint32_t base = sb;
        CP_ASYNC16(base + aoff,                gA);
        CP_ASYNC16(base + 4096 + aoff,         gA + RSTEP);
        CP_ASYNC16(base + OPB + aoff,          gBh);
        CP_ASYNC16(base + OPB + 4096 + aoff,   gBh + RSTEP);
        CP_ASYNC16(base + 2*OPB + aoff,        gBl);
        CP_ASYNC16(base + 2*OPB + 4096 + aoff, gBl + RSTEP);
        CP_COMMIT();
    }

    #pragma unroll 1
    for (int kc = 0; kc < NCH; kc++) {
        CP_WAIT0();          // chunk kc landed (this thread's group)
        __syncthreads();     // all threads' copies visible; prev stage readers done

        // issue chunk kc+1 into the other stage (its readers finished last iter)
        if (kc + 1 < NCH) {
            uint32_t base = sb + (uint32_t)((kc + 1) & 1) * STAGEB;
            size_t ko = (size_t)(kc + 1) * KCH;
            CP_ASYNC16(base + aoff,                gA + ko);
            CP_ASYNC16(base + 4096 + aoff,         gA + RSTEP + ko);
            CP_ASYNC16(base + OPB + aoff,          gBh + ko);
            CP_ASYNC16(base + OPB + 4096 + aoff,   gBh + RSTEP + ko);
            CP_ASYNC16(base + 2*OPB + aoff,        gBl + ko);
            CP_ASYNC16(base + 2*OPB + 4096 + aoff, gBl + RSTEP + ko);
            CP_COMMIT();
        }

        uint32_t stage = (uint32_t)(kc & 1) * STAGEB;
        uint32_t ah_t = sb + stage + offA;
        uint32_t bh_t = sb + stage + OPB + offB;
        uint32_t bl_t = sb + stage + 2 * OPB + offB;

        #pragma unroll
        for (int ks = 0; ks < 2; ks++) {
            uint32_t atomA = ((uint32_t)ks * 2 + selA) ^ swzA;
            uint32_t atomB = ((uint32_t)ks * 2 + selB) ^ swzB;
            uint32_t Ah[4][4], Bh[2][4], Bl[2][4];
            #pragma unroll
            for (int mi = 0; mi < 4; mi++)
                LDSM4(Ah[mi], ah_t + (uint32_t)mi * 1024 + (atomA << 4));
            #pragma unroll
            for (int nj = 0; nj < 2; nj++) {
                LDSM4(Bh[nj], bh_t + (uint32_t)nj * 1024 + (atomB << 4));
                LDSM4(Bl[nj], bl_t + (uint32_t)nj * 1024 + (atomB << 4));
            }
            #pragma unroll
            for (int mi = 0; mi < 4; mi++) {
                #pragma unroll
                for (int nf = 0; nf < 4; nf++) {
                    int nj = nf >> 1, h = (nf & 1) * 2;
                    MMA16816(c[mi][nf], Ah[mi], Bh[nj][h], Bh[nj][h + 1]);
                    MMA16816(c[mi][nf], Ah[mi], Bl[nj][h], Bl[nj][h + 1]);
                }
            }
        }
    }

    // epilogue: L2 -> u + u^2 + u^4 + u^8 + u^16 (sq norms straight from L2)
    float c16 = g_c16;
    float tsum = 0.f;
    #pragma unroll
    for (int mi = 0; mi < 4; mi++) {
        int r0 = warp_m * 64 + mi * 16 + (l >> 2);
        float sa0 = g_sq[arow + r0], sa1 = g_sq[arow + r0 + 8];
        #pragma unroll
        for (int nf = 0; nf < 4; nf++) {
            int j0 = warp_n * 32 + nf * 8 + 2 * (l & 3);
            float sb0 = g_sq[brow + j0], sb1 = g_sq[brow + j0 + 1];
            #pragma unroll
            for (int q = 0; q < 4; q++) {
                float sa  = (q < 2) ? sa0 : sa1;
                float sbv = (q & 1) ? sb1 : sb0;
                float L2  = sa + sbv - 2.f * c[mi][nf][q];
                float u   = ex2_approx(-L2 * c16);
                float u2 = u * u, u4 = u2 * u2, u8 = u4 * u4, u16 = u8 * u8;
                tsum += ((u + u2) + (u4 + u8)) + u16;
            }
        }
    }

    // warp shfl reduce, then 8 partials via reused sbuf
    #pragma unroll
    for (int o = 16; o; o >>= 1) tsum += __shfl_xor_sync(0xffffffffu, tsum, o);
    float* red = (float*)sbuf;
    __syncthreads();                 // mainloop smem reads complete
    if (l == 0) red[wid] = tsum;
    __syncthreads();
    if (tid == 0) {
        float s = 0.f;
        #pragma unroll
        for (int w = 0; w < 8; w++) s += red[w];
        double wt = ((bi < NT / 2) == (bj < NT / 2)) ? 1.0 : -1.0;
        if (bi != bj) wt *= 2.0;
        g_partial[blockIdx.x] = wt * (double)s;
    }
}

// -------- kernel 5: deterministic final reduction --------
__global__ void k_final(float* __restrict__ out) {
    __shared__ double s[256];
    int tid = threadIdx.x;
    double acc = 0.0;
    for (int i = tid; i < NTILES; i += 256) acc += g_partial[i];
    s[tid] = acc;
    __syncthreads();
    #pragma unroll
    for (int o = 128; o; o >>= 1) {
        if (tid < o) s[tid] += s[tid + o];
        __syncthreads();
    }
    if (tid == 0) out[0] = (float)(s[0] / ((double)BHALF * (double)BHALF));
}

extern "C" void kernel_launch(void* const* d_in, const int* in_sizes, int n_in,
                              void* d_out, int out_size) {
    const float* src = (const float*)d_in[0];
    const float* tgt = (const float*)d_in[1];
    float* out = (float*)d_out;

    k_prep<<<NROWS / 8, 256>>>(src, tgt);
    k_colsum<<<NCHUNK, 512>>>(src, tgt);
    k_scalar<<<1, 512>>>();
    k_mmd_hmma<<<NTILES, 256>>>();
    k_final<<<1, 256>>>(out);
}

// round 15
// speedup vs baseline: 6.2530x; 1.5075x over previous
#include <cuda_runtime.h>
#include <cuda_bf16.h>
#include <cstdint>

// Problem constants
#define D        512
#define NROWS    8192
#define BHALF    4096
#define BM       128
#define BN       128
#define NT       64                 // tiles per dim (8192/128)
#define NTILES   2080               // NT*(NT+1)/2, bj >= bi
#define NCHUNK   32
#define KCH      32                 // bf16 K elems per chunk
#define NCH      (D / KCH)          // 16 chunks
#define OPB      8192               // 128 rows x 64 B (swizzled, no pad)
#define STAGEB   (2 * OPB)          // Ah, Bh = 16384 B
#define NSTAGE   3
#define TOTB     (NSTAGE * STAGEB)  // 49152 B = 48 KB static

// -------- device scratch --------
__device__ __align__(16) __nv_bfloat16 g_hi[NROWS * D];
__device__ float  g_sq[NROWS];
__device__ float  g_colpart[NCHUNK][D];
__device__ float  g_c16;
__device__ double g_partial[NTILES];

// -------- helpers --------
__device__ __forceinline__ uint32_t smem_u32(const void* p) {
    uint32_t a;
    asm("{ .reg .u64 t; cvta.to.shared.u64 t, %1; cvt.u32.u64 %0, t; }" : "=r"(a) : "l"(p));
    return a;
}
__device__ __forceinline__ float ex2_approx(float x) {
    float y; asm("ex2.approx.ftz.f32 %0, %1;" : "=f"(y) : "f"(x)); return y;
}
#define LDSM4(r, a) \
    asm volatile("ldmatrix.sync.aligned.m8n8.x4.shared.b16 {%0,%1,%2,%3}, [%4];" \
        : "=r"((r)[0]), "=r"((r)[1]), "=r"((r)[2]), "=r"((r)[3]) : "r"(a))
#define MMA16816(c, A, b0, b1) \
    asm volatile("mma.sync.aligned.m16n8k16.row.col.f32.bf16.bf16.f32 " \
        "{%0,%1,%2,%3}, {%4,%5,%6,%7}, {%8,%9}, {%0,%1,%2,%3};" \
        : "+f"((c)[0]), "+f"((c)[1]), "+f"((c)[2]), "+f"((c)[3]) \
        : "r"((A)[0]), "r"((A)[1]), "r"((A)[2]), "r"((A)[3]), "r"(b0), "r"(b1))
#define CP_ASYNC16(dst, src) \
    asm volatile("cp.async.cg.shared.global [%0], [%1], 16;" :: "r"(dst), "l"(src) : "memory")
#define CP_COMMIT()  asm volatile("cp.async.commit_group;" ::: "memory")
#define CP_WAIT0()   asm volatile("cp.async.wait_group 0;" ::: "memory")
#define CP_WAIT1()   asm volatile("cp.async.wait_group 1;" ::: "memory")

// -------- kernel 1: fused per-row sq-norm + bf16 hi split (one pass) --------
// grid 1024, block 256: 8 warps -> 8 rows per block
__global__ void k_prep(const float* __restrict__ src, const float* __restrict__ tgt) {
    int row  = blockIdx.x * 8 + (threadIdx.x >> 5);
    int lane = threadIdx.x & 31;
    const float* p = (row < BHALF) ? (src + (size_t)row * D)
                                   : (tgt + (size_t)(row - BHALF) * D);
    const float4* p4 = (const float4*)p;
    float s = 0.f;
    #pragma unroll
    for (int c = lane; c < D / 4; c += 32) {
        float4 v = p4[c];
        s += v.x * v.x + v.y * v.y + v.z * v.z + v.w * v.w;
        __nv_bfloat16 h0 = __float2bfloat16_rn(v.x);
        __nv_bfloat16 h1 = __float2bfloat16_rn(v.y);
        __nv_bfloat16 h2 = __float2bfloat16_rn(v.z);
        __nv_bfloat16 h3 = __float2bfloat16_rn(v.w);
        uint32_t p0 = (uint32_t)__bfloat16_as_ushort(h0) | ((uint32_t)__bfloat16_as_ushort(h1) << 16);
        uint32_t p1 = (uint32_t)__bfloat16_as_ushort(h2) | ((uint32_t)__bfloat16_as_ushort(h3) << 16);
        size_t elem = (size_t)row * D + (size_t)c * 4;
        *(uint2*)(g_hi + elem) = make_uint2(p0, p1);
    }
    #pragma unroll
    for (int o = 16; o; o >>= 1) s += __shfl_xor_sync(0xffffffffu, s, o);
    if (lane == 0) g_sq[row] = s;
}

// -------- kernel 2: column-sum partials --------
__global__ void k_colsum(const float* __restrict__ src, const float* __restrict__ tgt) {
    int c = blockIdx.x;
    int d = threadIdx.x;
    const float* base = (c < NCHUNK / 2) ? (src + (size_t)c * 256 * D)
                                         : (tgt + (size_t)(c - NCHUNK / 2) * 256 * D);
    float s = 0.f;
    for (int r = 0; r < 256; r++) s += base[(size_t)r * D + d];
    g_colpart[c][d] = s;
}

// -------- kernel 3: bandwidth scalar --------
__global__ void k_scalar() {
    int d = threadIdx.x;
    float cs = 0.f;
    #pragma unroll
    for (int c = 0; c < NCHUNK; c++) cs += g_colpart[c][d];
    double v  = (double)cs * (double)cs;
    double sq = 0.0;
    #pragma unroll
    for (int k = 0; k < NROWS / D; k++) sq += (double)g_sq[d + D * k];
    __shared__ double s1[512], s2[512];
    s1[d] = v; s2[d] = sq;
    __syncthreads();
    for (int o = 256; o; o >>= 1) {
        if (d < o) { s1[d] += s1[d + o]; s2[d] += s2[d + o]; }
        __syncthreads();
    }
    if (d == 0) {
        double n     = (double)NROWS;
        double sumL2 = 2.0 * n * s2[0] - 2.0 * s1[0];
        double bw    = sumL2 / (n * n - n) / 4.0;
        g_c16 = (float)(1.4426950408889634 / (bw * 16.0));
    }
}

// -------- kernel 4: HMMA bf16 GEMM + RBF epilogue --------
// 256 threads, 48 KB static smem, 3-stage cp.async pipeline (2 in flight),
// 2 CTAs/SM. dot(x,y) ~= x_hi . y_hi (err random, ~sqrt2 x previous)
__global__ void __launch_bounds__(256, 2) k_mmd_hmma() {
    __shared__ __align__(128) char sbuf[TOTB];

    int tid = threadIdx.x;
    int wid = tid >> 5, l = tid & 31;
    int warp_m = wid >> 2;          // 0..1 -> 64-row slab
    int warp_n = wid & 3;           // 0..3 -> 32-col slab

    // tile decode: blockIdx -> (bi, bj), bj >= bi
    int t = blockIdx.x, bi = 0, rl = NT;
    while (t >= rl) { t -= rl; bi++; rl--; }
    int bj = bi + t;

    uint32_t sb = smem_u32(sbuf);
    const uint32_t arow = (uint32_t)bi * BM;
    const uint32_t brow = (uint32_t)bj * BN;

    // loader: thread -> (r = tid>>2 in 0..63, seg = tid&3); 4 slots:
    //   Ah rows r, r+64 ; Bh rows r, r+64
    int r   = tid >> 2, seg = tid & 3;
    uint32_t atom = (uint32_t)seg ^ (((uint32_t)r >> 1) & 3);
    uint32_t aoff = (uint32_t)r * 64 + (atom << 4);
    const __nv_bfloat16* gA = g_hi + ((size_t)(arow + r) * D + seg * 8);
    const __nv_bfloat16* gB = g_hi + ((size_t)(brow + r) * D + seg * 8);
    const size_t RSTEP = (size_t)64 * D;   // +64 rows

    // per-lane ldmatrix row/swizzle
    uint32_t rowA = (uint32_t)warp_m * 64 + (l & 15);
    uint32_t swzA = (rowA >> 1) & 3;
    uint32_t offA = rowA * 64;
    uint32_t selA = (uint32_t)(l >> 4);
    uint32_t rowB = (uint32_t)warp_n * 32 + (l & 7) + ((l >> 4) << 3);
    uint32_t swzB = (rowB >> 1) & 3;
    uint32_t offB = rowB * 64;
    uint32_t selB = (uint32_t)((l >> 3) & 1);

    float c[4][4][4];
    #pragma unroll
    for (int mi = 0; mi < 4; mi++)
        #pragma unroll
        for (int nf = 0; nf < 4; nf++)
            #pragma unroll
            for (int q = 0; q < 4; q++) c[mi][nf][q] = 0.f;

    // prologue: issue chunks 0 and 1 into stages 0 and 1
    #pragma unroll
    for (int pc = 0; pc < 2; pc++) {
        uint32_t base = sb + (uint32_t)pc * STAGEB;
        size_t ko = (size_t)pc * KCH;
        CP_ASYNC16(base + aoff,              gA + ko);
        CP_ASYNC16(base + 4096 + aoff,       gA + RSTEP + ko);
        CP_ASYNC16(base + OPB + aoff,        gB + ko);
        CP_ASYNC16(base + OPB + 4096 + aoff, gB + RSTEP + ko);
        CP_COMMIT();
    }

    int stage = 0;                  // stage holding chunk kc
    #pragma unroll 1
    for (int kc = 0; kc < NCH; kc++) {
        if (kc + 1 < NCH) CP_WAIT1(); else CP_WAIT0();   // chunk kc landed
        __syncthreads();            // visible to all; prev readers of next-issue stage done

        // issue chunk kc+2 into the stage freed at iteration kc-1
        if (kc + 2 < NCH) {
            int nst = stage + 2; if (nst >= NSTAGE) nst -= NSTAGE;
            uint32_t base = sb + (uint32_t)nst * STAGEB;
            size_t ko = (size_t)(kc + 2) * KCH;
            CP_ASYNC16(base + aoff,              gA + ko);
            CP_ASYNC16(base + 4096 + aoff,       gA + RSTEP + ko);
            CP_ASYNC16(base + OPB + aoff,        gB + ko);
            CP_ASYNC16(base + OPB + 4096 + aoff, gB + RSTEP + ko);
            CP_COMMIT();
        }

        uint32_t st   = sb + (uint32_t)stage * STAGEB;
        uint32_t ah_t = st + offA;
        uint32_t bh_t = st + OPB + offB;

        #pragma unroll
        for (int ks = 0; ks < 2; ks++) {
            uint32_t atomA = ((uint32_t)ks * 2 + selA) ^ swzA;
            uint32_t atomB = ((uint32_t)ks * 2 + selB) ^ swzB;
            uint32_t Ah[4][4], Bh[2][4];
            #pragma unroll
            for (int mi = 0; mi < 4; mi++)
                LDSM4(Ah[mi], ah_t + (uint32_t)mi * 1024 + (atomA << 4));
            #pragma unroll
            for (int nj = 0; nj < 2; nj++)
                LDSM4(Bh[nj], bh_t + (uint32_t)nj * 1024 + (atomB << 4));
            #pragma unroll
            for (int mi = 0; mi < 4; mi++) {
                #pragma unroll
                for (int nf = 0; nf < 4; nf++) {
                    int nj = nf >> 1, h = (nf & 1) * 2;
                    MMA16816(c[mi][nf], Ah[mi], Bh[nj][h], Bh[nj][h + 1]);
                }
            }
        }
        if (++stage >= NSTAGE) stage = 0;
    }

    // epilogue: L2 -> u + u^2 + u^4 + u^8 + u^16 (sq norms straight from L2)
    float c16 = g_c16;
    float tsum = 0.f;
    #pragma unroll
    for (int mi = 0; mi < 4; mi++) {
        int r0 = warp_m * 64 + mi * 16 + (l >> 2);
        float sa0 = g_sq[arow + r0], sa1 = g_sq[arow + r0 + 8];
        #pragma unroll
        for (int nf = 0; nf < 4; nf++) {
            int j0 = warp_n * 32 + nf * 8 + 2 * (l & 3);
            float sb0 = g_sq[brow + j0], sb1 = g_sq[brow + j0 + 1];
            #pragma unroll
            for (int q = 0; q < 4; q++) {
                float sa  = (q < 2) ? sa0 : sa1;
                float sbv = (q & 1) ? sb1 : sb0;
                float L2  = sa + sbv - 2.f * c[mi][nf][q];
                float u   = ex2_approx(-L2 * c16);
                float u2 = u * u, u4 = u2 * u2, u8 = u4 * u4, u16 = u8 * u8;
                tsum += ((u + u2) + (u4 + u8)) + u16;
            }
        }
    }

    // warp shfl reduce, then 8 partials via reused sbuf
    #pragma unroll
    for (int o = 16; o; o >>= 1) tsum += __shfl_xor_sync(0xffffffffu, tsum, o);
    float* red = (float*)sbuf;
    __syncthreads();                 // mainloop smem reads complete
    if (l == 0) red[wid] = tsum;
    __syncthreads();
    if (tid == 0) {
        float s = 0.f;
        #pragma unroll
        for (int w = 0; w < 8; w++) s += red[w];
        double wt = ((bi < NT / 2) == (bj < NT / 2)) ? 1.0 : -1.0;
        if (bi != bj) wt *= 2.0;
        g_partial[blockIdx.x] = wt * (double)s;
    }
}

// -------- kernel 5: deterministic final reduction --------
__global__ void k_final(float* __restrict__ out) {
    __shared__ double s[256];
    int tid = threadIdx.x;
    double acc = 0.0;
    for (int i = tid; i < NTILES; i += 256) acc += g_partial[i];
    s[tid] = acc;
    __syncthreads();
    #pragma unroll
    for (int o = 128; o; o >>= 1) {
        if (tid < o) s[tid] += s[tid + o];
        __syncthreads();
    }
    if (tid == 0) out[0] = (float)(s[0] / ((double)BHALF * (double)BHALF));
}

extern "C" void kernel_launch(void* const* d_in, const int* in_sizes, int n_in,
                              void* d_out, int out_size) {
    const float* src = (const float*)d_in[0];
    const float* tgt = (const float*)d_in[1];
    float* out = (float*)d_out;

    k_prep<<<NROWS / 8, 256>>>(src, tgt);
    k_colsum<<<NCHUNK, 512>>>(src, tgt);
    k_scalar<<<1, 512>>>();
    k_mmd_hmma<<<NTILES, 256>>>();
    k_final<<<1, 256>>>(out);
}